// round 17
// baseline (speedup 1.0000x reference)
#include <cuda_runtime.h>

#define Bn 8
#define Dn 192
#define Ln 4096
#define Nn 16
#define Rn 6
#define Cn 38
#define Kn 4
#define NC 32
#define Lc 128
#define XP 65   // padded row length for xt (conflict-free d-fast reads)

// scratch (allocation-free device globals); DU padded 4 steps for prefetch ring
__device__ float g_DU[(size_t)Bn*Kn*Ln*Dn*2 + Dn*8];
__device__ float g_B [(size_t)Bn*Kn*Ln*Nn];
__device__ float g_C [(size_t)Bn*Kn*Ln*Nn];
__device__ float g_ys[(size_t)Bn*Kn*Ln*Dn];
__device__ float g_hend[(size_t)Bn*Kn*NC*Dn*Nn];
__device__ float g_S[(size_t)Bn*Kn*NC*Dn];

__device__ __forceinline__ float ex2f(float x){
    float r; asm("ex2.approx.ftz.f32 %0, %1;" : "=f"(r) : "f"(x)); return r;
}
__device__ __forceinline__ float lg2f(float x){
    float r; asm("lg2.approx.ftz.f32 %0, %1;" : "=f"(r) : "f"(x)); return r;
}
__device__ __forceinline__ void cp16(void* smem_dst, const void* gmem_src){
    unsigned s = (unsigned)__cvta_generic_to_shared(smem_dst);
    asm volatile("cp.async.cg.shared.global [%0], [%1], 16;" :: "r"(s), "l"(gmem_src));
}
__device__ __forceinline__ void cp_commit(){ asm volatile("cp.async.commit_group;"); }
__device__ __forceinline__ void cp_wait1(){ asm volatile("cp.async.wait_group 1;"); }
__device__ __forceinline__ void cp_wait0(){ asm volatile("cp.async.wait_group 0;"); }

// ---------------------------------------------------------------------------
// Kernel A: cross-scan gather + x_proj + dt_proj + softplus. (R16 config)
// ---------------------------------------------------------------------------
__global__ __launch_bounds__(256, 3) void proj_kernel(
    const float* __restrict__ x, const float* __restrict__ xpw,
    const float* __restrict__ dtw, const float* __restrict__ dtb)
{
    __shared__ float xt[Dn*XP];
    __shared__ float dts_s[Rn][64];
    __shared__ float sB[16][65];
    __shared__ float sC[16][65];

    const int bid = blockIdx.x;
    const int t   = bid & 63;
    const int k   = (bid >> 6) & 3;
    const int b   = bid >> 8;
    const int tid = threadIdx.x;

    int p0, pstep;
    if (k == 2) { p0 = 4095 - t*64; pstep = -1; }
    else        { p0 = t*64;        pstep = 1;  }

    const float* xb = x + (size_t)b*Dn*Ln;
    for (int idx = tid; idx < Dn*64; idx += 256) {
        int d = idx >> 6, j = idx & 63;
        xt[d*XP + j] = xb[(size_t)d*Ln + p0 + j*pstep];
    }
    __syncthreads();

    auto lof = [&](int j) -> int {
        if (k == 1) return j*64 + t;
        if (k == 3) return 4095 - j*64 - t;
        return t*64 + j;
    };

    {
        const int j = tid & 31;
        const int w = tid >> 5;

        float acc[5][2];
        #pragma unroll
        for (int m = 0; m < 5; m++) { acc[m][0] = 0.f; acc[m][1] = 0.f; }
        const float4* wp[5];
        #pragma unroll
        for (int m = 0; m < 5; m++) {
            int c = w + 8*m; if (c > Cn-1) c = Cn-1;
            wp[m] = (const float4*)(xpw + (size_t)(k*Cn + c)*Dn);
        }
        #pragma unroll 2
        for (int i = 0; i < Dn/4; i++) {
            float a0 = xt[(4*i+0)*XP + j],  b0 = xt[(4*i+0)*XP + j+32];
            float a1 = xt[(4*i+1)*XP + j],  b1 = xt[(4*i+1)*XP + j+32];
            float a2 = xt[(4*i+2)*XP + j],  b2 = xt[(4*i+2)*XP + j+32];
            float a3 = xt[(4*i+3)*XP + j],  b3 = xt[(4*i+3)*XP + j+32];
            #pragma unroll
            for (int m = 0; m < 5; m++) {
                float4 wv = wp[m][i];
                acc[m][0] = fmaf(wv.x, a0, acc[m][0]);
                acc[m][1] = fmaf(wv.x, b0, acc[m][1]);
                acc[m][0] = fmaf(wv.y, a1, acc[m][0]);
                acc[m][1] = fmaf(wv.y, b1, acc[m][1]);
                acc[m][0] = fmaf(wv.z, a2, acc[m][0]);
                acc[m][1] = fmaf(wv.z, b2, acc[m][1]);
                acc[m][0] = fmaf(wv.w, a3, acc[m][0]);
                acc[m][1] = fmaf(wv.w, b3, acc[m][1]);
            }
        }
        #pragma unroll
        for (int m = 0; m < 5; m++) {
            int c = w + 8*m;
            if (c < Rn) { dts_s[c][j] = acc[m][0]; dts_s[c][j+32] = acc[m][1]; }
            else if (c < Cn) {
                int n = c - Rn;
                if (n < Nn) { sB[n][j] = acc[m][0]; sB[n][j+32] = acc[m][1]; }
                else        { int nn = n - Nn;
                              sC[nn][j] = acc[m][0]; sC[nn][j+32] = acc[m][1]; }
            }
        }
    }
    __syncthreads();

    {
        const int pos = tid >> 2, nq = tid & 3;
        float4 vB, vC;
        vB.x = sB[4*nq+0][pos]; vB.y = sB[4*nq+1][pos];
        vB.z = sB[4*nq+2][pos]; vB.w = sB[4*nq+3][pos];
        vC.x = sC[4*nq+0][pos]; vC.y = sC[4*nq+1][pos];
        vC.z = sC[4*nq+2][pos]; vC.w = sC[4*nq+3][pos];
        const size_t base = ((size_t)(b*Kn + k)*Ln + lof(pos))*(size_t)Nn + 4*nq;
        *(float4*)&g_B[base] = vB;
        *(float4*)&g_C[base] = vC;
    }

    if (tid < 96) {
        const int d0 = 2*tid;
        float wr0[6], wr1[6];
        #pragma unroll
        for (int r = 0; r < Rn; r++) {
            wr0[r] = dtw[(k*Dn + d0)*Rn + r];
            wr1[r] = dtw[(k*Dn + d0 + 1)*Rn + r];
        }
        const float bias0 = dtb[k*Dn + d0];
        const float bias1 = dtb[k*Dn + d0 + 1];
        const float* xr0 = xt + d0*XP;
        const float* xr1 = xt + (d0+1)*XP;
        float4* dub = ((float4*)g_DU) + (size_t)(b*Kn + k)*Ln*(Dn/2) + tid;
        #pragma unroll 2
        for (int j = 0; j < 64; j++) {
            float acc0 = bias0, acc1 = bias1;
            #pragma unroll
            for (int r = 0; r < Rn; r++) {
                float s = dts_s[r][j];
                acc0 = fmaf(s, wr0[r], acc0);
                acc1 = fmaf(s, wr1[r], acc1);
            }
            float e0 = ex2f(acc0 * 1.4426950408889634f);
            float sp0 = 0.6931471805599453f * lg2f(1.f + e0);
            if (acc0 > 20.f) sp0 = acc0;
            float e1 = ex2f(acc1 * 1.4426950408889634f);
            float sp1 = 0.6931471805599453f * lg2f(1.f + e1);
            if (acc1 > 20.f) sp1 = acc1;
            dub[(size_t)lof(j)*(Dn/2)] = make_float4(sp0, xr0[j], sp1, xr1[j]);
        }
    }
}

// ---------------------------------------------------------------------------
// Scan pass 1: grid=512, 2 jobs/block {bid, bid+512}, cp.async double-buffered
// B staging -> single wave, job-2 prologue hidden. A regs shared (same k,d).
// ---------------------------------------------------------------------------
__global__ __launch_bounds__(192, 4) void scan_p1(const float* __restrict__ A_logs)
{
    __shared__ float4 sB[2][Lc*4];
    const int d = threadIdx.x;
    const int job0 = blockIdx.x;            // bk in [0,16)
    const int k  = (job0 >> 5) & 3;

    // async stage both jobs (job1 = job0+512 -> bk+16, same k)
    {
        const float4* gb0 = (const float4*)(g_B + ((size_t)(job0 >> 5)*Ln + (size_t)(job0 & 31)*Lc)*16);
        for (int i = d; i < Lc*4; i += 192) cp16(&sB[0][i], gb0 + i);
        cp_commit();
        const int job1 = job0 + 512;
        const float4* gb1 = (const float4*)(g_B + ((size_t)(job1 >> 5)*Ln + (size_t)(job1 & 31)*Lc)*16);
        for (int i = d; i < Lc*4; i += 192) cp16(&sB[1][i], gb1 + i);
        cp_commit();
    }

    float A[16];
    {
        const float4* al = (const float4*)(A_logs + (size_t)(k*Dn + d)*16);
        #pragma unroll
        for (int m = 0; m < 4; m++) {
            float4 v = al[m];
            A[4*m+0] = -expf(v.x) * 1.4426950408889634f;
            A[4*m+1] = -expf(v.y) * 1.4426950408889634f;
            A[4*m+2] = -expf(v.z) * 1.4426950408889634f;
            A[4*m+3] = -expf(v.w) * 1.4426950408889634f;
        }
    }
    cp_wait1();
    __syncthreads();

    #pragma unroll
    for (int jj = 0; jj < 2; jj++) {
        const int job = job0 + jj*512;
        const int bk = job >> 5;
        const int c  = job & 31;

        float h[16];
        #pragma unroll
        for (int n = 0; n < 16; n++) h[n] = 0.f;
        float S = 0.f;

        const float2* du = ((const float2*)g_DU) + ((size_t)bk*Ln + (size_t)c*Lc)*Dn + d;
        float2 ring[4];
        #pragma unroll
        for (int i = 0; i < 4; i++) ring[i] = du[(size_t)i*Dn];
        du += 4*Dn;

        float dA[16];
        #pragma unroll
        for (int n = 0; n < 16; n++) dA[n] = ex2f(ring[0].x * A[n]);

        const float4* sBj = sB[jj];
        #pragma unroll 4
        for (int t = 0; t < Lc; t++) {
            float2 cur = ring[t & 3];
            ring[t & 3] = du[0]; du += Dn;
            float dt = cur.x, dtu = dt*cur.y;
            S += dt;
            #pragma unroll
            for (int m = 0; m < 4; m++) {
                float4 q = sBj[t*4 + m];
                h[4*m+0] = fmaf(dA[4*m+0], h[4*m+0], dtu*q.x);
                h[4*m+1] = fmaf(dA[4*m+1], h[4*m+1], dtu*q.y);
                h[4*m+2] = fmaf(dA[4*m+2], h[4*m+2], dtu*q.z);
                h[4*m+3] = fmaf(dA[4*m+3], h[4*m+3], dtu*q.w);
            }
            float dtn = ring[(t+1) & 3].x;
            #pragma unroll
            for (int n = 0; n < 16; n++) dA[n] = ex2f(dtn * A[n]);
        }

        float4* out = (float4*)(g_hend + (((size_t)bk*NC + c)*Dn + d)*16);
        #pragma unroll
        for (int m = 0; m < 4; m++) out[m] = make_float4(h[4*m], h[4*m+1], h[4*m+2], h[4*m+3]);
        g_S[((size_t)bk*NC + c)*Dn + d] = S;

        if (jj == 0) { cp_wait0(); __syncthreads(); }
    }
}

// ---------------------------------------------------------------------------
// Scan mid: chain chunk summaries -> exclusive h_init prefix (in place).
// ---------------------------------------------------------------------------
__global__ __launch_bounds__(256) void scan_mid(const float* __restrict__ A_logs)
{
    int gid = blockIdx.x*256 + threadIdx.x;
    if (gid >= 32*Dn*Nn) return;
    int n  = gid & 15;
    int d  = (gid >> 4) % Dn;
    int bk = gid / (Dn*16);
    int k  = bk & 3;
    float A = -expf(A_logs[(size_t)(k*Dn + d)*16 + n]) * 1.4426950408889634f;
    float h = 0.f;
    for (int c = 0; c < NC; c++) {
        size_t o = (((size_t)bk*NC + c)*Dn + d)*16 + n;
        float hend = g_hend[o];
        float S = g_S[((size_t)bk*NC + c)*Dn + d];
        g_hend[o] = h;
        h = fmaf(ex2f(A*S), h, hend);
    }
}

// ---------------------------------------------------------------------------
// Scan pass 2: grid=512, 2 jobs/block, cp.async double-buffered B+C staging.
// ---------------------------------------------------------------------------
__global__ __launch_bounds__(192, 4) void scan_p2(
    const float* __restrict__ A_logs, const float* __restrict__ Ds)
{
    __shared__ float4 sB[2][Lc*4];
    __shared__ float4 sC[2][Lc*4];
    const int d = threadIdx.x;
    const int job0 = blockIdx.x;
    const int k  = (job0 >> 5) & 3;

    {
        size_t off0 = ((size_t)(job0 >> 5)*Ln + (size_t)(job0 & 31)*Lc)*16;
        const float4* gb0 = (const float4*)(g_B + off0);
        const float4* gc0 = (const float4*)(g_C + off0);
        for (int i = d; i < Lc*4; i += 192) { cp16(&sB[0][i], gb0 + i); cp16(&sC[0][i], gc0 + i); }
        cp_commit();
        const int job1 = job0 + 512;
        size_t off1 = ((size_t)(job1 >> 5)*Ln + (size_t)(job1 & 31)*Lc)*16;
        const float4* gb1 = (const float4*)(g_B + off1);
        const float4* gc1 = (const float4*)(g_C + off1);
        for (int i = d; i < Lc*4; i += 192) { cp16(&sB[1][i], gb1 + i); cp16(&sC[1][i], gc1 + i); }
        cp_commit();
    }

    float A[16];
    {
        const float4* al = (const float4*)(A_logs + (size_t)(k*Dn + d)*16);
        #pragma unroll
        for (int m = 0; m < 4; m++) {
            float4 v = al[m];
            A[4*m+0] = -expf(v.x) * 1.4426950408889634f;
            A[4*m+1] = -expf(v.y) * 1.4426950408889634f;
            A[4*m+2] = -expf(v.z) * 1.4426950408889634f;
            A[4*m+3] = -expf(v.w) * 1.4426950408889634f;
        }
    }
    const float Dd = Ds[k*Dn + d];
    cp_wait1();
    __syncthreads();

    #pragma unroll
    for (int jj = 0; jj < 2; jj++) {
        const int job = job0 + jj*512;
        const int bk = job >> 5;
        const int c  = job & 31;

        float h[16];
        {
            const float4* hin = (const float4*)(g_hend + (((size_t)bk*NC + c)*Dn + d)*16);
            #pragma unroll
            for (int m = 0; m < 4; m++) {
                float4 v = hin[m];
                h[4*m+0] = v.x; h[4*m+1] = v.y; h[4*m+2] = v.z; h[4*m+3] = v.w;
            }
        }

        const float2* du = ((const float2*)g_DU) + ((size_t)bk*Ln + (size_t)c*Lc)*Dn + d;
        float* yo = g_ys + ((size_t)bk*Ln + (size_t)c*Lc)*Dn + d;

        float2 ring[4];
        #pragma unroll
        for (int i = 0; i < 4; i++) ring[i] = du[(size_t)i*Dn];
        du += 4*Dn;

        float dA[16];
        #pragma unroll
        for (int n = 0; n < 16; n++) dA[n] = ex2f(ring[0].x * A[n]);

        const float4* sBj = sB[jj];
        const float4* sCj = sC[jj];
        #pragma unroll 4
        for (int t = 0; t < Lc; t++) {
            float2 cur = ring[t & 3];
            ring[t & 3] = du[0]; du += Dn;
            float dt = cur.x, u = cur.y, dtu = dt*u;
            float pa = 0.f, pb = 0.f;
            #pragma unroll
            for (int m = 0; m < 4; m++) {
                float4 q = sBj[t*4 + m];
                float4 r = sCj[t*4 + m];
                h[4*m+0] = fmaf(dA[4*m+0], h[4*m+0], dtu*q.x);
                h[4*m+1] = fmaf(dA[4*m+1], h[4*m+1], dtu*q.y);
                h[4*m+2] = fmaf(dA[4*m+2], h[4*m+2], dtu*q.z);
                h[4*m+3] = fmaf(dA[4*m+3], h[4*m+3], dtu*q.w);
                pa = fmaf(h[4*m+0], r.x, pa);
                pb = fmaf(h[4*m+1], r.y, pb);
                pa = fmaf(h[4*m+2], r.z, pa);
                pb = fmaf(h[4*m+3], r.w, pb);
            }
            yo[(size_t)t*Dn] = fmaf(Dd, u, pa + pb);
            float dtn = ring[(t+1) & 3].x;
            #pragma unroll
            for (int n = 0; n < 16; n++) dA[n] = ex2f(dtn * A[n]);
        }

        if (jj == 0) { cp_wait0(); __syncthreads(); }
    }
}

// ---------------------------------------------------------------------------
// CrossMerge + LayerNorm.
// ---------------------------------------------------------------------------
__global__ __launch_bounds__(256) void merge_ln_kernel(
    const float* __restrict__ gamma, const float* __restrict__ beta,
    float* __restrict__ out)
{
    const int bid  = blockIdx.x;
    const int b    = bid >> 9;
    const int l    = ((bid & 511) << 3) + (threadIdx.x >> 5);
    const int lane = threadIdx.x & 31;
    const int hh = l >> 6, ww = l & 63;
    const int lT = ww*64 + hh;

    const float* y0 = g_ys + ((size_t)(b*4+0)*Ln + l)*Dn;
    const float* y1 = g_ys + ((size_t)(b*4+1)*Ln + lT)*Dn;
    const float* y2 = g_ys + ((size_t)(b*4+2)*Ln + (4095 - l))*Dn;
    const float* y3 = g_ys + ((size_t)(b*4+3)*Ln + (4095 - lT))*Dn;

    float v[6]; float s = 0.f;
    #pragma unroll
    for (int i = 0; i < 6; i++) {
        int dd = lane + 32*i;
        v[i] = y0[dd] + y1[dd] + y2[dd] + y3[dd];
        s += v[i];
    }
    #pragma unroll
    for (int o = 16; o; o >>= 1) s += __shfl_xor_sync(0xffffffffu, s, o);
    float mean = s * (1.f/192.f);
    float var = 0.f;
    #pragma unroll
    for (int i = 0; i < 6; i++) { float z = v[i] - mean; var = fmaf(z, z, var); }
    #pragma unroll
    for (int o = 16; o; o >>= 1) var += __shfl_xor_sync(0xffffffffu, var, o);
    float rstd = rsqrtf(var*(1.f/192.f) + 1e-5f);

    size_t ob = ((size_t)b*Ln + l)*Dn;
    #pragma unroll
    for (int i = 0; i < 6; i++) {
        int dd = lane + 32*i;
        out[ob + dd] = fmaf((v[i] - mean)*rstd, gamma[dd], beta[dd]);
    }
}

extern "C" void kernel_launch(void* const* d_in, const int* in_sizes, int n_in,
                              void* d_out, int out_size) {
    const float* x    = (const float*)d_in[0];
    const float* xpw  = (const float*)d_in[1];
    const float* dtw  = (const float*)d_in[2];
    const float* dtb  = (const float*)d_in[3];
    const float* Alog = (const float*)d_in[4];
    const float* Ds   = (const float*)d_in[5];
    const float* gam  = (const float*)d_in[6];
    const float* bet  = (const float*)d_in[7];
    float* out = (float*)d_out;

    proj_kernel<<<Bn*Kn*64, 256>>>(x, xpw, dtw, dtb);
    scan_p1<<<512, 192>>>(Alog);
    scan_mid<<<(32*Dn*Nn + 255)/256, 256>>>(Alog);
    scan_p2<<<512, 192>>>(Alog, Ds);
    merge_ln_kernel<<<Bn*512, 256>>>(gam, bet, out);
}